// round 16
// baseline (speedup 1.0000x reference)
#include <cuda_runtime.h>
#include <cuda_fp16.h>
#include <cuda_bf16.h>

#define B 512
#define S 1024
#define I 20
#define H 64
#define G 256    // 4*H gates
#define NB 7     // batches (chains) per LSTM CTA -> 74*2 = 148 CTAs = 1/SM
#define NCTA 74
#define HSH 72   // half-element stride of h rows in SMEM
#define GS 260   // float stride of s_gates rows [batch][gate]

// ---- scratch (device globals; no allocation allowed) ----
__device__ int   g_tok[B * S];
__device__ float g_h[2][B * H];

__device__ __forceinline__ unsigned pack_h2(float lo, float hi) {
    __half2 h = __floats2half2_rn(lo, hi);
    return *reinterpret_cast<unsigned*>(&h);
}
__device__ __forceinline__ __half2 h2tanh_fast(__half2 x) {
    unsigned xi = *reinterpret_cast<unsigned*>(&x);
    unsigned yi;
    asm("tanh.approx.f16x2 %0, %1;" : "=r"(yi) : "r"(xi));
    return *reinterpret_cast<__half2*>(&yi);
}
__device__ __forceinline__ __half2 sig2_fast(__half2 x, __half2 h05) {
    return __hfma2(h2tanh_fast(__hmul2(x, h05)), h05, h05);
}
__device__ __forceinline__ void mma_f16(float d[4],
                                        unsigned a0, unsigned a1,
                                        unsigned a2, unsigned a3,
                                        unsigned b0, unsigned b1) {
    asm volatile(
        "mma.sync.aligned.m16n8k16.row.col.f32.f16.f16.f32 "
        "{%0,%1,%2,%3}, {%4,%5,%6,%7}, {%8,%9}, {%0,%1,%2,%3};"
        : "+f"(d[0]), "+f"(d[1]), "+f"(d[2]), "+f"(d[3])
        : "r"(a0), "r"(a1), "r"(a2), "r"(a3), "r"(b0), "r"(b1));
}
__device__ __forceinline__ void ldsm_x4(unsigned& r0, unsigned& r1,
                                        unsigned& r2, unsigned& r3,
                                        unsigned addr) {
    asm volatile(
        "ldmatrix.sync.aligned.m8n8.x4.shared.b16 {%0,%1,%2,%3}, [%4];"
        : "=r"(r0), "=r"(r1), "=r"(r2), "=r"(r3) : "r"(addr));
}

// ============================================================
// Kernel 1: tokenize only. grid (B, 4) x 256 threads, 1 pos/thread.
// ============================================================
__global__ void __launch_bounds__(256) k_tok(const float* __restrict__ input1) {
    int b = blockIdx.x;
    int s = blockIdx.y * 256 + threadIdx.x;
    const float4* row = (const float4*)(input1 + ((size_t)b * S + s) * I);
    int t = -1;
    #pragma unroll
    for (int q = 0; q < 5; q++) {
        float4 v = row[q];
        if (v.x > 0.5f) t = q * 4 + 0;
        if (v.y > 0.5f) t = q * 4 + 1;
        if (v.z > 0.5f) t = q * 4 + 2;
        if (v.w > 0.5f) t = q * 4 + 3;
    }
    g_tok[b * S + s] = t;
}

// ============================================================
// Kernel 2: fp16 tensor-core LSTM (R8 structure; B operand via
// ldmatrix.x4 — 2 LDSM replace 8 LDS.32 per warp per step).
//   D[256 gates, 8 batch cols] = W_hh[256,64] @ h^T[64,8]
// ============================================================
__global__ void __launch_bounds__(256, 1)
k_lstm(const float* __restrict__ W_ih_f, const float* __restrict__ W_hh_f,
       const float* __restrict__ b_f,
       const float* __restrict__ W_ih_b, const float* __restrict__ W_hh_b,
       const float* __restrict__ b_b) {
    int b0  = blockIdx.x * NB;
    int dir = blockIdx.y;
    int t    = threadIdx.x;
    int w    = t >> 5;
    int lane = t & 31;
    int gID  = lane >> 2;      // 0..7
    int tig  = lane & 3;       // 0..3

    const float* W_ih = dir ? W_ih_b : W_ih_f;
    const float* W_hh = dir ? W_hh_b : W_hh_f;
    const float* bias = dir ? b_b    : b_f;

    __shared__ float  s_Wihb[21 * G];   // [tok][gate] bias-fused; row 20 = bias only
    __shared__ __half s_h[8 * HSH];     // h rows = batches 0..7 (row 7 stays 0)
    __shared__ float  s_gates[8 * GS];  // [batch][gate]
    __shared__ signed char s_tok[NB * S];

    for (int idx = t; idx < 21 * G; idx += 256) {
        int i  = idx >> 8;
        int gg = idx & 255;
        float v = bias[gg];
        if (i < I) v += W_ih[gg * I + i];
        s_Wihb[idx] = v;
    }
    for (int idx = t; idx < NB * S; idx += 256) {
        int nb = idx / S, s = idx & (S - 1);
        int bb = b0 + nb;
        s_tok[idx] = (bb < B) ? (signed char)g_tok[bb * S + s] : (signed char)-1;
    }
    for (int idx = t; idx < 8 * HSH / 2; idx += 256)
        ((unsigned*)s_h)[idx] = 0u;

    // A fragments: W_hh rows for this warp's 32 gates (2 m16 tiles x 4 K-chunks)
    unsigned af[4][2][4];
    #pragma unroll
    for (int kt = 0; kt < 4; kt++) {
        #pragma unroll
        for (int j = 0; j < 2; j++) {
            int gb = w * 32 + j * 16;
            int k0 = kt * 16 + 2 * tig;
            const float* r0 = W_hh + (gb + gID) * H;
            const float* r1 = W_hh + (gb + gID + 8) * H;
            af[kt][j][0] = pack_h2(r0[k0],     r0[k0 + 1]);
            af[kt][j][1] = pack_h2(r1[k0],     r1[k0 + 1]);
            af[kt][j][2] = pack_h2(r0[k0 + 8], r0[k0 + 9]);
            af[kt][j][3] = pack_h2(r1[k0 + 8], r1[k0 + 9]);
        }
    }

    // ldmatrix address: lane l -> row (batch) = l&7, k-chunk = l>>3 (8 halves)
    unsigned hb_addr = (unsigned)__cvta_generic_to_shared(s_h)
                     + (unsigned)(((lane & 7) * HSH + (lane >> 3) * 8) * 2);

    // activation role: warp ab handles batch ab (0..6), units 2*lane, 2*lane+1
    int ab = t >> 5;
    int ah = (t & 31) * 2;
    bool act = (ab < NB);
    float cs0 = 0.0f, cs1 = 0.0f;
    float hx = 0.0f, hy = 0.0f;
    const __half2 h05 = __float2half2_rn(0.5f);
    __syncthreads();

    for (int step = 0; step < S; step++) {
        int s = dir ? (S - 1 - step) : step;

        // ---- MMA phase: 2 LDSM.x4 + 8 mma/warp ----
        float d0[4] = {0.f, 0.f, 0.f, 0.f};
        float d1[4] = {0.f, 0.f, 0.f, 0.f};
        {
            unsigned q0, q1, q2, q3, q4, q5, q6, q7;
            ldsm_x4(q0, q1, q2, q3, hb_addr);        // k 0..31  (kt 0,1)
            ldsm_x4(q4, q5, q6, q7, hb_addr + 64);   // k 32..63 (kt 2,3)
            mma_f16(d0, af[0][0][0], af[0][0][1], af[0][0][2], af[0][0][3], q0, q1);
            mma_f16(d1, af[0][1][0], af[0][1][1], af[0][1][2], af[0][1][3], q0, q1);
            mma_f16(d0, af[1][0][0], af[1][0][1], af[1][0][2], af[1][0][3], q2, q3);
            mma_f16(d1, af[1][1][0], af[1][1][1], af[1][1][2], af[1][1][3], q2, q3);
            mma_f16(d0, af[2][0][0], af[2][0][1], af[2][0][2], af[2][0][3], q4, q5);
            mma_f16(d1, af[2][1][0], af[2][1][1], af[2][1][2], af[2][1][3], q4, q5);
            mma_f16(d0, af[3][0][0], af[3][0][1], af[3][0][2], af[3][0][3], q6, q7);
            mma_f16(d1, af[3][1][0], af[3][1][1], af[3][1][2], af[3][1][3], q6, q7);
        }
        // scatter D into [batch][gate] (conflict-free scalar stores)
        {
            int m0 = w * 32 + gID;
            int r0 = (2 * tig) * GS, r1 = (2 * tig + 1) * GS;
            s_gates[r0 + m0]      = d0[0];
            s_gates[r1 + m0]      = d0[1];
            s_gates[r0 + m0 + 8]  = d0[2];
            s_gates[r1 + m0 + 8]  = d0[3];
            s_gates[r0 + m0 + 16] = d1[0];
            s_gates[r1 + m0 + 16] = d1[1];
            s_gates[r0 + m0 + 24] = d1[2];
            s_gates[r1 + m0 + 24] = d1[3];
        }
        __syncthreads();

        // ---- activation phase (f16x2 nonlinearities, fp32 cell state) ----
        if (act) {
            int tok = s_tok[ab * S + s];
            int row = (tok >= 0) ? tok : 20;
            const float* gp = s_gates + ab * GS + ah;
            const float* ip = s_Wihb + row * G + ah;
            float2 mi = *(const float2*)(gp);
            float2 mf = *(const float2*)(gp + H);
            float2 mg = *(const float2*)(gp + 2 * H);
            float2 mo = *(const float2*)(gp + 3 * H);
            float2 ii = *(const float2*)(ip);
            float2 ff = *(const float2*)(ip + H);
            float2 gv = *(const float2*)(ip + 2 * H);
            float2 oo = *(const float2*)(ip + 3 * H);
            __half2 I2 = __floats2half2_rn(mi.x + ii.x, mi.y + ii.y);
            __half2 F2 = __floats2half2_rn(mf.x + ff.x, mf.y + ff.y);
            __half2 G2 = __floats2half2_rn(mg.x + gv.x, mg.y + gv.y);
            __half2 O2 = __floats2half2_rn(mo.x + oo.x, mo.y + oo.y);
            __half2 sI = sig2_fast(I2, h05);
            __half2 sF = sig2_fast(F2, h05);
            __half2 sO = sig2_fast(O2, h05);
            __half2 tG = h2tanh_fast(G2);
            float2 fF = __half22float2(sF);
            float2 pp = __half22float2(__hmul2(sI, tG));
            cs0 = fF.x * cs0 + pp.x;
            cs1 = fF.y * cs1 + pp.y;
            __half2 tC = h2tanh_fast(__floats2half2_rn(cs0, cs1));
            __half2 hv = __hmul2(sO, tC);
            *(__half2*)(s_h + ab * HSH + ah) = hv;
            float2 fh = __half22float2(hv);
            hx = fh.x; hy = fh.y;
        }
        __syncthreads();
    }

    if (act && (b0 + ab) < B)
        *(float2*)(&g_h[dir][(b0 + ab) * H + ah]) = make_float2(hx, hy);
}

// ============================================================
// Kernel 3: avblock + conv2+relu + concat + fc1 (split-K) + fc2 + softmax
// grid: B blocks x 256 threads
// ============================================================
__global__ void __launch_bounds__(256) k_head(
                       const float* __restrict__ conv1_w,
                       const float* __restrict__ conv2_w,
                       const float* __restrict__ conv2_b,
                       const float* __restrict__ fc1_w,
                       const float* __restrict__ fc1_b,
                       const float* __restrict__ fc2_w,
                       const float* __restrict__ fc2_b,
                       float* __restrict__ out) {
    int b = blockIdx.x;
    int tid = threadIdx.x;
    __shared__ int   s_tok[S];
    __shared__ float s_w1[I * I];
    __shared__ float s_m[232];
    __shared__ float s_av[80];
    __shared__ float s_fh[128];
    __shared__ float s_f[64];
    __shared__ int   s_c[9];

    int cnt = 0;
    for (int s = tid; s < S; s += 256) {
        int tk = g_tok[b * S + s];
        s_tok[s] = tk;
        cnt += (tk >= 0) ? 1 : 0;
    }
    #pragma unroll
    for (int o = 16; o > 0; o >>= 1) cnt += __shfl_xor_sync(0xffffffffu, cnt, o);
    if ((tid & 31) == 0) s_c[tid >> 5] = cnt;

    for (int i = tid; i < I * I; i += 256) s_w1[i] = conv1_w[i];
    if (tid < 64)            s_m[tid] = g_h[0][b * H + tid];
    else if (tid < 128)      s_m[tid] = g_h[1][b * H + tid - 64];
    if (tid >= 100 && tid < 104) s_m[128 + tid] = 0.0f;
    __syncthreads();

    if (tid == 0) {
        int tot = 0;
        #pragma unroll
        for (int i = 0; i < 8; i++) tot += s_c[i];
        s_c[8] = tot;
    }
    __syncthreads();

    int bw = s_c[8] / 4;
    if (tid < 80) {
        int k = tid / I, cc = tid % I;
        float sum = 0.0f;
        for (int s = k * bw; s < (k + 1) * bw; s++) {
            int flat = s * I + cc;
            int ch = flat >> 10;
            int pp = flat & (S - 1);
            int tk = s_tok[pp];
            if (tk >= 0) sum += s_w1[ch * I + tk];
        }
        s_av[tid] = sum / (float)bw;
    }
    __syncthreads();

    if (tid < 100) {
        float acc = conv2_b[tid];
        const float* w = conv2_w + tid * 80;
        float a0 = 0.f, a1 = 0.f, a2 = 0.f, a3 = 0.f;
        #pragma unroll
        for (int j = 0; j < 80; j += 4) {
            a0 = fmaf(s_av[j],     w[j],     a0);
            a1 = fmaf(s_av[j + 1], w[j + 1], a1);
            a2 = fmaf(s_av[j + 2], w[j + 2], a2);
            a3 = fmaf(s_av[j + 3], w[j + 3], a3);
        }
        s_m[128 + tid] = fmaxf(acc + (a0 + a1) + (a2 + a3), 0.0f);
    }
    __syncthreads();

    {
        int o    = tid & 127;
        int half = tid >> 7;
        if (o < 64) {
            const float* w = fc1_w + o * 228;
            int j0 = half ? 112 : 0;
            int j1 = half ? 228 : 112;
            float a0 = 0.f, a1 = 0.f, a2 = 0.f, a3 = 0.f;
            for (int j = j0; j < j1; j += 4) {
                a0 = fmaf(s_m[j],     w[j],     a0);
                a1 = fmaf(s_m[j + 1], w[j + 1], a1);
                a2 = fmaf(s_m[j + 2], w[j + 2], a2);
                a3 = fmaf(s_m[j + 3], w[j + 3], a3);
            }
            s_fh[half * 64 + o] = (a0 + a1) + (a2 + a3);
        }
    }
    __syncthreads();
    if (tid < 64) s_f[tid] = fc1_b[tid] + s_fh[tid] + s_fh[64 + tid];
    __syncthreads();

    if (tid < 32) {
        float v0 = s_f[tid], v1 = s_f[tid + 32];
        float p0 = v0 * fc2_w[tid]      + v1 * fc2_w[tid + 32];
        float p1 = v0 * fc2_w[64 + tid] + v1 * fc2_w[96 + tid];
        #pragma unroll
        for (int o = 16; o > 0; o >>= 1) {
            p0 += __shfl_xor_sync(0xffffffffu, p0, o);
            p1 += __shfl_xor_sync(0xffffffffu, p1, o);
        }
        if (tid == 0) {
            float a0 = p0 + fc2_b[0], a1 = p1 + fc2_b[1];
            float m  = fmaxf(a0, a1);
            float e0 = __expf(a0 - m), e1 = __expf(a1 - m);
            float inv = 1.0f / (e0 + e1);
            out[b * 2 + 0] = e0 * inv;
            out[b * 2 + 1] = e1 * inv;
        }
    }
}

extern "C" void kernel_launch(void* const* d_in, const int* in_sizes, int n_in,
                              void* d_out, int out_size) {
    const float* input1  = (const float*)d_in[0];
    const float* W_ih_f  = (const float*)d_in[1];
    const float* W_hh_f  = (const float*)d_in[2];
    const float* b_f     = (const float*)d_in[3];
    const float* W_ih_b  = (const float*)d_in[4];
    const float* W_hh_b  = (const float*)d_in[5];
    const float* b_b     = (const float*)d_in[6];
    const float* conv1_w = (const float*)d_in[7];
    const float* conv2_w = (const float*)d_in[8];
    const float* conv2_b = (const float*)d_in[9];
    const float* fc1_w   = (const float*)d_in[10];
    const float* fc1_b   = (const float*)d_in[11];
    const float* fc2_w   = (const float*)d_in[12];
    const float* fc2_b   = (const float*)d_in[13];
    float* out = (float*)d_out;

    dim3 tgrid(B, 4);
    k_tok<<<tgrid, 256>>>(input1);
    dim3 lgrid(NCTA, 2);
    k_lstm<<<lgrid, 256>>>(W_ih_f, W_hh_f, b_f, W_ih_b, W_hh_b, b_b);
    k_head<<<B, 256>>>(conv1_w, conv2_w, conv2_b, fc1_w, fc1_b,
                       fc2_w, fc2_b, out);
}

// round 17
// speedup vs baseline: 1.0167x; 1.0167x over previous
#include <cuda_runtime.h>
#include <cuda_fp16.h>
#include <cuda_bf16.h>

#define B 512
#define S 1024
#define I 20
#define H 64
#define G 256    // 4*H gates
#define NB 7     // batches (chains) per LSTM CTA -> 74*2 = 148 CTAs = 1/SM
#define NCTA 74
#define HSH 72   // half-element stride of h rows in SMEM
#define GS 260   // float stride of s_gates rows [batch][gate]

// ---- scratch (device globals; no allocation allowed) ----
__device__ int   g_tok[B * S];
__device__ float g_h[2][B * H];

__device__ __forceinline__ unsigned pack_h2(float lo, float hi) {
    __half2 h = __floats2half2_rn(lo, hi);
    return *reinterpret_cast<unsigned*>(&h);
}
__device__ __forceinline__ __half2 h2tanh_fast(__half2 x) {
    unsigned xi = *reinterpret_cast<unsigned*>(&x);
    unsigned yi;
    asm("tanh.approx.f16x2 %0, %1;" : "=r"(yi) : "r"(xi));
    return *reinterpret_cast<__half2*>(&yi);
}
__device__ __forceinline__ __half2 sig2_fast(__half2 x, __half2 h05) {
    return __hfma2(h2tanh_fast(__hmul2(x, h05)), h05, h05);
}
__device__ __forceinline__ void mma_f16(float d[4],
                                        unsigned a0, unsigned a1,
                                        unsigned a2, unsigned a3,
                                        unsigned b0, unsigned b1) {
    asm volatile(
        "mma.sync.aligned.m16n8k16.row.col.f32.f16.f16.f32 "
        "{%0,%1,%2,%3}, {%4,%5,%6,%7}, {%8,%9}, {%0,%1,%2,%3};"
        : "+f"(d[0]), "+f"(d[1]), "+f"(d[2]), "+f"(d[3])
        : "r"(a0), "r"(a1), "r"(a2), "r"(a3), "r"(b0), "r"(b1));
}

// ============================================================
// Kernel 1: tokenize only. grid (B, 4) x 256 threads, 1 pos/thread.
// ============================================================
__global__ void __launch_bounds__(256) k_tok(const float* __restrict__ input1) {
    int b = blockIdx.x;
    int s = blockIdx.y * 256 + threadIdx.x;
    const float4* row = (const float4*)(input1 + ((size_t)b * S + s) * I);
    int t = -1;
    #pragma unroll
    for (int q = 0; q < 5; q++) {
        float4 v = row[q];
        if (v.x > 0.5f) t = q * 4 + 0;
        if (v.y > 0.5f) t = q * 4 + 1;
        if (v.z > 0.5f) t = q * 4 + 2;
        if (v.w > 0.5f) t = q * 4 + 3;
    }
    g_tok[b * S + s] = t;
}

// ============================================================
// Kernel 2: fp16 tensor-core LSTM (exact R8/R14 structure — FROZEN).
//   D[256 gates, 8 batch cols] = W_hh[256,64] @ h^T[64,8]
// 8 warps; warp w owns gate rows [32w, 32w+32) = 2 m16 tiles.
// W_hh lives in A-fragments (32 regs/warp) for all 1024 steps.
// Batch column 7 is padding (s_h row 7 stays zero).
// ============================================================
__global__ void __launch_bounds__(256, 1)
k_lstm(const float* __restrict__ W_ih_f, const float* __restrict__ W_hh_f,
       const float* __restrict__ b_f,
       const float* __restrict__ W_ih_b, const float* __restrict__ W_hh_b,
       const float* __restrict__ b_b) {
    int b0  = blockIdx.x * NB;
    int dir = blockIdx.y;
    int t    = threadIdx.x;
    int w    = t >> 5;
    int lane = t & 31;
    int gID  = lane >> 2;      // 0..7
    int tig  = lane & 3;       // 0..3

    const float* W_ih = dir ? W_ih_b : W_ih_f;
    const float* W_hh = dir ? W_hh_b : W_hh_f;
    const float* bias = dir ? b_b    : b_f;

    __shared__ float  s_Wihb[21 * G];   // [tok][gate] bias-fused; row 20 = bias only
    __shared__ __half s_h[8 * HSH];     // h rows = batches 0..7 (row 7 stays 0)
    __shared__ float  s_gates[8 * GS];  // [batch][gate]
    __shared__ signed char s_tok[NB * S];

    for (int idx = t; idx < 21 * G; idx += 256) {
        int i  = idx >> 8;
        int gg = idx & 255;
        float v = bias[gg];
        if (i < I) v += W_ih[gg * I + i];
        s_Wihb[idx] = v;
    }
    for (int idx = t; idx < NB * S; idx += 256) {
        int nb = idx / S, s = idx & (S - 1);
        int bb = b0 + nb;
        s_tok[idx] = (bb < B) ? (signed char)g_tok[bb * S + s] : (signed char)-1;
    }
    for (int idx = t; idx < 8 * HSH / 2; idx += 256)
        ((unsigned*)s_h)[idx] = 0u;

    // A fragments: W_hh rows for this warp's 32 gates (2 m16 tiles x 4 K-chunks)
    unsigned af[4][2][4];
    #pragma unroll
    for (int kt = 0; kt < 4; kt++) {
        #pragma unroll
        for (int j = 0; j < 2; j++) {
            int gb = w * 32 + j * 16;
            int k0 = kt * 16 + 2 * tig;
            const float* r0 = W_hh + (gb + gID) * H;
            const float* r1 = W_hh + (gb + gID + 8) * H;
            af[kt][j][0] = pack_h2(r0[k0],     r0[k0 + 1]);
            af[kt][j][1] = pack_h2(r1[k0],     r1[k0 + 1]);
            af[kt][j][2] = pack_h2(r0[k0 + 8], r0[k0 + 9]);
            af[kt][j][3] = pack_h2(r1[k0 + 8], r1[k0 + 9]);
        }
    }

    // activation role: warp ab handles batch ab (0..6), units 2*lane, 2*lane+1
    int ab = t >> 5;
    int ah = (t & 31) * 2;
    bool act = (ab < NB);
    float cs0 = 0.0f, cs1 = 0.0f;
    float hx = 0.0f, hy = 0.0f;
    const __half2 h05 = __float2half2_rn(0.5f);
    __syncthreads();

    for (int step = 0; step < S; step++) {
        int s = dir ? (S - 1 - step) : step;

        // ---- MMA phase: 8 mma/warp, B-frags shared across the 2 M tiles ----
        float d0[4] = {0.f, 0.f, 0.f, 0.f};
        float d1[4] = {0.f, 0.f, 0.f, 0.f};
        #pragma unroll
        for (int kt = 0; kt < 4; kt++) {
            int k0 = kt * 16 + 2 * tig;
            unsigned bb0 = *(const unsigned*)(s_h + gID * HSH + k0);
            unsigned bb1 = *(const unsigned*)(s_h + gID * HSH + k0 + 8);
            mma_f16(d0, af[kt][0][0], af[kt][0][1], af[kt][0][2], af[kt][0][3], bb0, bb1);
            mma_f16(d1, af[kt][1][0], af[kt][1][1], af[kt][1][2], af[kt][1][3], bb0, bb1);
        }
        // scatter D into [batch][gate] (conflict-free scalar stores)
        {
            int m0 = w * 32 + gID;
            int r0 = (2 * tig) * GS, r1 = (2 * tig + 1) * GS;
            s_gates[r0 + m0]      = d0[0];
            s_gates[r1 + m0]      = d0[1];
            s_gates[r0 + m0 + 8]  = d0[2];
            s_gates[r1 + m0 + 8]  = d0[3];
            s_gates[r0 + m0 + 16] = d1[0];
            s_gates[r1 + m0 + 16] = d1[1];
            s_gates[r0 + m0 + 24] = d1[2];
            s_gates[r1 + m0 + 24] = d1[3];
        }
        __syncthreads();

        // ---- activation phase (f16x2 nonlinearities, fp32 cell state) ----
        if (act) {
            int tok = s_tok[ab * S + s];
            int row = (tok >= 0) ? tok : 20;
            const float* gp = s_gates + ab * GS + ah;
            const float* ip = s_Wihb + row * G + ah;
            float2 mi = *(const float2*)(gp);
            float2 mf = *(const float2*)(gp + H);
            float2 mg = *(const float2*)(gp + 2 * H);
            float2 mo = *(const float2*)(gp + 3 * H);
            float2 ii = *(const float2*)(ip);
            float2 ff = *(const float2*)(ip + H);
            float2 gv = *(const float2*)(ip + 2 * H);
            float2 oo = *(const float2*)(ip + 3 * H);
            __half2 I2 = __floats2half2_rn(mi.x + ii.x, mi.y + ii.y);
            __half2 F2 = __floats2half2_rn(mf.x + ff.x, mf.y + ff.y);
            __half2 G2 = __floats2half2_rn(mg.x + gv.x, mg.y + gv.y);
            __half2 O2 = __floats2half2_rn(mo.x + oo.x, mo.y + oo.y);
            __half2 sI = sig2_fast(I2, h05);
            __half2 sF = sig2_fast(F2, h05);
            __half2 sO = sig2_fast(O2, h05);
            __half2 tG = h2tanh_fast(G2);
            float2 fF = __half22float2(sF);
            float2 pp = __half22float2(__hmul2(sI, tG));
            cs0 = fF.x * cs0 + pp.x;
            cs1 = fF.y * cs1 + pp.y;
            __half2 tC = h2tanh_fast(__floats2half2_rn(cs0, cs1));
            __half2 hv = __hmul2(sO, tC);
            *(__half2*)(s_h + ab * HSH + ah) = hv;
            float2 fh = __half22float2(hv);
            hx = fh.x; hy = fh.y;
        }
        __syncthreads();
    }

    if (act && (b0 + ab) < B)
        *(float2*)(&g_h[dir][(b0 + ab) * H + ah]) = make_float2(hx, hy);
}

// ============================================================
// Kernel 3: avblock (3-way split) + conv2+relu + fc1 (split-K) + fc2 + softmax
// grid: B blocks x 256 threads
// ============================================================
__global__ void __launch_bounds__(256) k_head(
                       const float* __restrict__ conv1_w,
                       const float* __restrict__ conv2_w,
                       const float* __restrict__ conv2_b,
                       const float* __restrict__ fc1_w,
                       const float* __restrict__ fc1_b,
                       const float* __restrict__ fc2_w,
                       const float* __restrict__ fc2_b,
                       float* __restrict__ out) {
    int b = blockIdx.x;
    int tid = threadIdx.x;
    __shared__ int   s_tok[S];
    __shared__ float s_w1[I * I];
    __shared__ float s_m[232];
    __shared__ float s_pav[3][80];
    __shared__ float s_av[80];
    __shared__ float s_fh[128];
    __shared__ float s_f[64];
    __shared__ int   s_c[9];

    int cnt = 0;
    for (int s = tid; s < S; s += 256) {
        int tk = g_tok[b * S + s];
        s_tok[s] = tk;
        cnt += (tk >= 0) ? 1 : 0;
    }
    #pragma unroll
    for (int o = 16; o > 0; o >>= 1) cnt += __shfl_xor_sync(0xffffffffu, cnt, o);
    if ((tid & 31) == 0) s_c[tid >> 5] = cnt;

    for (int i = tid; i < I * I; i += 256) s_w1[i] = conv1_w[i];
    if (tid < 64)            s_m[tid] = g_h[0][b * H + tid];
    else if (tid < 128)      s_m[tid] = g_h[1][b * H + tid - 64];
    if (tid >= 100 && tid < 104) s_m[128 + tid] = 0.0f;
    __syncthreads();

    if (tid == 0) {
        int tot = 0;
        #pragma unroll
        for (int i = 0; i < 8; i++) tot += s_c[i];
        s_c[8] = tot;
    }
    __syncthreads();

    // avblock: conv1 token-gather + torch-reshape + ragged 4-bin mean,
    // 3-way segment split (240 threads -> 3 partial sums per (bin,chan))
    int bw = s_c[8] / 4;
    if (tid < 240) {
        int seg = tid / 80;
        int idx = tid - seg * 80;
        int k = idx / I, cc = idx % I;
        int s0 = k * bw + (seg * bw) / 3;
        int s1 = k * bw + ((seg + 1) * bw) / 3;
        float sum = 0.0f;
        for (int s = s0; s < s1; s++) {
            int flat = s * I + cc;
            int ch = flat >> 10;       // flat / S  (S=1024)
            int pp = flat & (S - 1);   // flat % S
            int tk = s_tok[pp];
            if (tk >= 0) sum += s_w1[ch * I + tk];
        }
        s_pav[seg][idx] = sum;
    }
    __syncthreads();
    if (tid < 80)
        s_av[tid] = (s_pav[0][tid] + s_pav[1][tid] + s_pav[2][tid]) / (float)bw;
    __syncthreads();

    // conv2 + relu -> s_m[128..227]
    if (tid < 100) {
        float acc = conv2_b[tid];
        const float* w = conv2_w + tid * 80;
        float a0 = 0.f, a1 = 0.f, a2 = 0.f, a3 = 0.f;
        #pragma unroll
        for (int j = 0; j < 80; j += 4) {
            a0 = fmaf(s_av[j],     w[j],     a0);
            a1 = fmaf(s_av[j + 1], w[j + 1], a1);
            a2 = fmaf(s_av[j + 2], w[j + 2], a2);
            a3 = fmaf(s_av[j + 3], w[j + 3], a3);
        }
        s_m[128 + tid] = fmaxf(acc + (a0 + a1) + (a2 + a3), 0.0f);
    }
    __syncthreads();

    // fc1 with 2-way K split
    {
        int o    = tid & 127;
        int half = tid >> 7;
        if (o < 64) {
            const float* w = fc1_w + o * 228;
            int j0 = half ? 112 : 0;
            int j1 = half ? 228 : 112;
            float a0 = 0.f, a1 = 0.f, a2 = 0.f, a3 = 0.f;
            for (int j = j0; j < j1; j += 4) {
                a0 = fmaf(s_m[j],     w[j],     a0);
                a1 = fmaf(s_m[j + 1], w[j + 1], a1);
                a2 = fmaf(s_m[j + 2], w[j + 2], a2);
                a3 = fmaf(s_m[j + 3], w[j + 3], a3);
            }
            s_fh[half * 64 + o] = (a0 + a1) + (a2 + a3);
        }
    }
    __syncthreads();
    if (tid < 64) s_f[tid] = fc1_b[tid] + s_fh[tid] + s_fh[64 + tid];
    __syncthreads();

    if (tid < 32) {
        float v0 = s_f[tid], v1 = s_f[tid + 32];
        float p0 = v0 * fc2_w[tid]      + v1 * fc2_w[tid + 32];
        float p1 = v0 * fc2_w[64 + tid] + v1 * fc2_w[96 + tid];
        #pragma unroll
        for (int o = 16; o > 0; o >>= 1) {
            p0 += __shfl_xor_sync(0xffffffffu, p0, o);
            p1 += __shfl_xor_sync(0xffffffffu, p1, o);
        }
        if (tid == 0) {
            float a0 = p0 + fc2_b[0], a1 = p1 + fc2_b[1];
            float m  = fmaxf(a0, a1);
            float e0 = __expf(a0 - m), e1 = __expf(a1 - m);
            float inv = 1.0f / (e0 + e1);
            out[b * 2 + 0] = e0 * inv;
            out[b * 2 + 1] = e1 * inv;
        }
    }
}

extern "C" void kernel_launch(void* const* d_in, const int* in_sizes, int n_in,
                              void* d_out, int out_size) {
    const float* input1  = (const float*)d_in[0];
    const float* W_ih_f  = (const float*)d_in[1];
    const float* W_hh_f  = (const float*)d_in[2];
    const float* b_f     = (const float*)d_in[3];
    const float* W_ih_b  = (const float*)d_in[4];
    const float* W_hh_b  = (const float*)d_in[5];
    const float* b_b     = (const float*)d_in[6];
    const float* conv1_w = (const float*)d_in[7];
    const float* conv2_w = (const float*)d_in[8];
    const float* conv2_b = (const float*)d_in[9];
    const float* fc1_w   = (const float*)d_in[10];
    const float* fc1_b   = (const float*)d_in[11];
    const float* fc2_w   = (const float*)d_in[12];
    const float* fc2_b   = (const float*)d_in[13];
    float* out = (float*)d_out;

    dim3 tgrid(B, 4);
    k_tok<<<tgrid, 256>>>(input1);
    dim3 lgrid(NCTA, 2);
    k_lstm<<<lgrid, 256>>>(W_ih_f, W_hh_f, b_f, W_ih_b, W_hh_b, b_b);
    k_head<<<B, 256>>>(conv1_w, conv2_w, conv2_b, fc1_w, fc1_b,
                       fc2_w, fc2_b, out);
}